// round 6
// baseline (speedup 1.0000x reference)
#include <cuda_runtime.h>
#include <cuda_bf16.h>
#include <cstdint>

#define BB 2
#define HH 32
#define SS 16384
#define DD 64
#define NHEADS (BB*HH)
#define SPLIT 64
#define CHUNK (SS/SPLIT)   /* 256 */
#define TS 32

/* phase2 tensor-core config */
#define TM 128                        /* s-rows per tile */
#define NTILES (NHEADS * (SS / TM))   /* 8192 */
#define TIT 4                         /* tiles per CTA (head fixed per CTA) */
#define GRID2 (NTILES / TIT)          /* 2048 */

/* scratch (no runtime alloc) */
__device__ float g_part[(size_t)NHEADS * SPLIT * 4160];
__device__ float g_norm[(size_t)NHEADS * 64];
__device__ __nv_bfloat16 g_memT_hi[(size_t)NHEADS * 4096];  /* [head][dv*64+dk] */
__device__ __nv_bfloat16 g_memT_lo[(size_t)NHEADS * 4096];

__device__ __forceinline__ float elu1(float x) {
    return x > 0.0f ? x + 1.0f : __expf(x);
}

/* ---- warp-level tensor core primitives (baseline PTX, no sm_103a needed) ---- */
__device__ __forceinline__ uint32_t smem_u32(const void* p) {
    uint32_t a;
    asm("{ .reg .u64 t; cvta.to.shared.u64 t, %1; cvt.u32.u64 %0, t; }" : "=r"(a) : "l"(p));
    return a;
}
__device__ __forceinline__ void ldsm_x4(uint32_t& r0, uint32_t& r1, uint32_t& r2,
                                        uint32_t& r3, uint32_t addr) {
    asm volatile("ldmatrix.sync.aligned.m8n8.x4.shared.b16 {%0,%1,%2,%3}, [%4];"
                 : "=r"(r0), "=r"(r1), "=r"(r2), "=r"(r3) : "r"(addr));
}
__device__ __forceinline__ void mma_bf16(float* d, const uint32_t* a,
                                         uint32_t b0, uint32_t b1) {
    asm volatile(
        "mma.sync.aligned.m16n8k16.row.col.f32.bf16.bf16.f32 "
        "{%0,%1,%2,%3}, {%4,%5,%6,%7}, {%8,%9}, {%0,%1,%2,%3};"
        : "+f"(d[0]), "+f"(d[1]), "+f"(d[2]), "+f"(d[3])
        : "r"(a[0]), "r"(a[1]), "r"(a[2]), "r"(a[3]), "r"(b0), "r"(b1));
}

/* swizzled byte offset: 128B rows, 16B units XOR'ed by row&7 (conflict-free ldmatrix) */
#define ASWZ(row, unit) (((uint32_t)(row) << 7) + ((((unit) ^ ((row) & 7)) & 7) << 4))

/* ------------- Phase 1: per-chunk partial memory + norm (scalar 8x4, best measured) ------------- */
__global__ void __launch_bounds__(128) phase1(const float* __restrict__ kk,
                                              const float* __restrict__ vv) {
    __shared__ float sk[TS][64];
    __shared__ float sv[TS][64];

    const int bx    = blockIdx.x;
    const int head  = bx / SPLIT;
    const int chunk = bx % SPLIT;
    const int tid   = threadIdx.x;
    const int dk0   = (tid >> 4) * 8;
    const int dv0   = (tid & 15) * 4;

    float acc[8][4] = {};
    float nrm[8]    = {};

    const float* kbase = kk + ((size_t)head * SS + (size_t)chunk * CHUNK) * DD;
    const float* vbase = vv + ((size_t)head * SS + (size_t)chunk * CHUNK) * DD;

    for (int it = 0; it < CHUNK / TS; ++it) {
        __syncthreads();
        #pragma unroll
        for (int p = 0; p < 4; ++p) {
            int f = tid + p * 128;
            int r = f >> 4;
            int c = (f & 15) * 4;
            float4 kf = *(const float4*)(kbase + (size_t)(it * TS + r) * DD + c);
            kf.x = elu1(kf.x); kf.y = elu1(kf.y); kf.z = elu1(kf.z); kf.w = elu1(kf.w);
            *(float4*)&sk[r][c] = kf;
            *(float4*)&sv[r][c] = *(const float4*)(vbase + (size_t)(it * TS + r) * DD + c);
        }
        __syncthreads();

        #pragma unroll 4
        for (int s = 0; s < TS; ++s) {
            float4 ka = *(float4*)&sk[s][dk0];
            float4 kb = *(float4*)&sk[s][dk0 + 4];
            float4 vv4 = *(float4*)&sv[s][dv0];
            float kfv[8] = {ka.x, ka.y, ka.z, ka.w, kb.x, kb.y, kb.z, kb.w};
            float vvv[4] = {vv4.x, vv4.y, vv4.z, vv4.w};
            #pragma unroll
            for (int i = 0; i < 8; ++i)
                #pragma unroll
                for (int j = 0; j < 4; ++j)
                    acc[i][j] += kfv[i] * vvv[j];
            if (dv0 == 0) {
                #pragma unroll
                for (int i = 0; i < 8; ++i) nrm[i] += kfv[i];
            }
        }
    }

    float* outp = g_part + (size_t)bx * 4160;
    #pragma unroll
    for (int i = 0; i < 8; ++i) {
        *(float4*)&outp[(dk0 + i) * 64 + dv0] =
            make_float4(acc[i][0], acc[i][1], acc[i][2], acc[i][3]);
    }
    if (dv0 == 0) {
        *(float4*)&outp[4096 + dk0]     = make_float4(nrm[0], nrm[1], nrm[2], nrm[3]);
        *(float4*)&outp[4096 + dk0 + 4] = make_float4(nrm[4], nrm[5], nrm[6], nrm[7]);
    }
}

/* ------- Reduce: sum SPLIT partials; emit transposed bf16 hi/lo memory + fp32 norm ------- */
__global__ void __launch_bounds__(512) reduce_k() {
    const int head = blockIdx.x;
    for (int e = threadIdx.x; e < 4160; e += 512) {
        float s = 0.f;
        #pragma unroll 8
        for (int c = 0; c < SPLIT; ++c)
            s += g_part[((size_t)head * SPLIT + c) * 4160 + e];
        if (e < 4096) {
            int dk = e >> 6, dv = e & 63;
            __nv_bfloat16 h = __float2bfloat16(s);
            __nv_bfloat16 l = __float2bfloat16(s - __bfloat162float(h));
            g_memT_hi[(size_t)head * 4096 + dv * 64 + dk] = h;
            g_memT_lo[(size_t)head * 4096 + dv * 64 + dk] = l;
        } else {
            g_norm[(size_t)head * 64 + (e - 4096)] = s;
        }
    }
}

/* ---------------- Phase 2: mma.sync bf16x3 retrieval GEMM ---------------- */
/* dynamic smem: A hi (16K) | A lo (16K) | B hi (8K) | B lo (8K) = 48K exactly.
   NO static __shared__ — total must stay <= 49152 default per-block limit. */
#define SM_AH 0
#define SM_AL 16384
#define SM_BH 32768
#define SM_BL 40960
#define SM_DYN_TOTAL 49152

__global__ void __launch_bounds__(128) phase2_mma(const float* __restrict__ q,
                                                  float* __restrict__ outg) {
    extern __shared__ __align__(128) char dyn[];

    const int tid  = threadIdx.x;
    const int wid  = tid >> 5;
    const int lane = tid & 31;
    const uint32_t sb = smem_u32(dyn);

    const int t0   = blockIdx.x * TIT;
    const int head = t0 >> 7;            /* constant across the CTA's TIT tiles */

    /* ---- per-CTA load: memory matrix (bf16 hi/lo, swizzled) ---- */
    {
        const __nv_bfloat16* bh = g_memT_hi + (size_t)head * 4096;
        const __nv_bfloat16* bl = g_memT_lo + (size_t)head * 4096;
        #pragma unroll
        for (int p = 0; p < 4; ++p) {
            int f = tid + p * 128;       /* 16B-unit index 0..511 */
            int r = f >> 3;              /* dv row 0..63 */
            int u = f & 7;
            uint32_t off = ASWZ(r, u);
            *(uint4*)(dyn + SM_BH + off) = *(const uint4*)(bh + r * 64 + u * 8);
            *(uint4*)(dyn + SM_BL + off) = *(const uint4*)(bl + r * 64 + u * 8);
        }
    }
    __syncthreads();

    const float4* nrm4 = (const float4*)(g_norm + (size_t)head * 64);
    const int wrow = wid * 32;           /* this warp's first m-row */

    for (int it = 0; it < TIT; ++it) {
        const int t  = t0 + it;
        const int s0 = (t & 127) * TM;   /* first seq row of this tile */

        /* ---- per-lane Q row: elu, denominator, bf16 split, swizzled store ---- */
        __syncwarp();
        float den = 0.f;
        {
            const int row = tid;
            const float4* qrow =
                (const float4*)(q + ((size_t)head * SS + (size_t)(s0 + row)) * DD);
            #pragma unroll
            for (int i = 0; i < 16; ++i) {
                float4 v = qrow[i];
                v.x = elu1(v.x); v.y = elu1(v.y); v.z = elu1(v.z); v.w = elu1(v.w);
                float4 nv = __ldg(&nrm4[i]);
                den += v.x * nv.x + v.y * nv.y + v.z * nv.z + v.w * nv.w;
                __nv_bfloat16 hx = __float2bfloat16(v.x), hy = __float2bfloat16(v.y);
                __nv_bfloat16 hz = __float2bfloat16(v.z), hw = __float2bfloat16(v.w);
                __nv_bfloat16 lx = __float2bfloat16(v.x - __bfloat162float(hx));
                __nv_bfloat16 ly = __float2bfloat16(v.y - __bfloat162float(hy));
                __nv_bfloat16 lz = __float2bfloat16(v.z - __bfloat162float(hz));
                __nv_bfloat16 lw = __float2bfloat16(v.w - __bfloat162float(hw));
                uint2 hp, lp;
                hp.x = (uint32_t)__bfloat16_as_ushort(hx) | ((uint32_t)__bfloat16_as_ushort(hy) << 16);
                hp.y = (uint32_t)__bfloat16_as_ushort(hz) | ((uint32_t)__bfloat16_as_ushort(hw) << 16);
                lp.x = (uint32_t)__bfloat16_as_ushort(lx) | ((uint32_t)__bfloat16_as_ushort(ly) << 16);
                lp.y = (uint32_t)__bfloat16_as_ushort(lz) | ((uint32_t)__bfloat16_as_ushort(lw) << 16);
                uint32_t off = ASWZ(row, i >> 1) + (i & 1) * 8;
                *(uint2*)(dyn + SM_AH + off) = hp;
                *(uint2*)(dyn + SM_AL + off) = lp;
            }
        }
        __syncwarp();

        /* ---- 3-pass bf16 mma: hh + hl + lh ---- */
        float acc[2][8][4];
        #pragma unroll
        for (int mi = 0; mi < 2; ++mi)
            #pragma unroll
            for (int nt = 0; nt < 8; ++nt)
                #pragma unroll
                for (int e = 0; e < 4; ++e) acc[mi][nt][e] = 0.f;

        #pragma unroll
        for (int ps = 0; ps < 3; ++ps) {
            const uint32_t abase = sb + ((ps == 2) ? SM_AL : SM_AH);
            const uint32_t bbase = sb + ((ps == 1) ? SM_BL : SM_BH);
            #pragma unroll
            for (int kt = 0; kt < 4; ++kt) {
                uint32_t a[2][4];
                #pragma unroll
                for (int mi = 0; mi < 2; ++mi) {
                    int ar = wrow + mi * 16 + (lane & 15);
                    ldsm_x4(a[mi][0], a[mi][1], a[mi][2], a[mi][3],
                            abase + ASWZ(ar, kt * 2 + (lane >> 4)));
                }
                uint32_t b[8][2];
                #pragma unroll
                for (int np = 0; np < 4; ++np) {
                    int br = np * 16 + (lane & 7) + ((lane >> 4) << 3);
                    uint32_t r0, r1, r2, r3;
                    ldsm_x4(r0, r1, r2, r3,
                            bbase + ASWZ(br, kt * 2 + ((lane >> 3) & 1)));
                    b[np*2+0][0] = r0; b[np*2+0][1] = r1;
                    b[np*2+1][0] = r2; b[np*2+1][1] = r3;
                }
                #pragma unroll
                for (int mi = 0; mi < 2; ++mi)
                    #pragma unroll
                    for (int nt = 0; nt < 8; ++nt)
                        mma_bf16(acc[mi][nt], a[mi], b[nt][0], b[nt][1]);
            }
        }

        /* ---- epilogue: denominators via warp shuffle, divide, store ---- */
        float* obase = outg + ((size_t)head * SS + (size_t)s0) * DD;
        #pragma unroll
        for (int mi = 0; mi < 2; ++mi) {
            int src_lo = mi * 16 + (lane >> 2);      /* lane holding den of r_lo */
            float inv_lo = 1.0f / __shfl_sync(0xffffffffu, den, src_lo);
            float inv_hi = 1.0f / __shfl_sync(0xffffffffu, den, src_lo + 8);
            int r_lo = wrow + mi * 16 + (lane >> 2);
            int r_hi = r_lo + 8;
            #pragma unroll
            for (int nt = 0; nt < 8; ++nt) {
                int col = nt * 8 + (lane & 3) * 2;
                *(float2*)(obase + (size_t)r_lo * DD + col) =
                    make_float2(acc[mi][nt][0] * inv_lo, acc[mi][nt][1] * inv_lo);
                *(float2*)(obase + (size_t)r_hi * DD + col) =
                    make_float2(acc[mi][nt][2] * inv_hi, acc[mi][nt][3] * inv_hi);
            }
        }
    }
}

extern "C" void kernel_launch(void* const* d_in, const int* in_sizes, int n_in,
                              void* d_out, int out_size) {
    const float* q = (const float*)d_in[0];
    const float* k = (const float*)d_in[1];
    const float* v = (const float*)d_in[2];
    float* out = (float*)d_out;

    /* idempotent opt-in (immediate host call, not stream-captured) */
    cudaFuncSetAttribute(phase2_mma, cudaFuncAttributeMaxDynamicSharedMemorySize,
                         SM_DYN_TOTAL);

    phase1<<<NHEADS * SPLIT, 128>>>(k, v);
    reduce_k<<<NHEADS, 512>>>();
    phase2_mma<<<GRID2, 128, SM_DYN_TOTAL>>>(q, out);
}